// round 8
// baseline (speedup 1.0000x reference)
#include <cuda_runtime.h>
#include <cuda_bf16.h>
#include <cstdint>

#define N_NODES 100000
#define N_EDGES 1600000
#define NFEAT   512
#define NHID    256
#define NCLASS  40
#define NF4     (NCLASS / 4)

#define SCAN_T  1024
#define NBLK    ((N_NODES + SCAN_T - 1) / SCAN_T)   // 98

// ---------------- scratch (static device globals; no allocation) ----------------
__device__ float g_h1[(size_t)N_NODES * NHID];
__device__ float g_h2[(size_t)N_NODES * NHID];
__device__ float g_h [(size_t)N_NODES * NCLASS];
__device__ float g_vA[(size_t)N_NODES * NCLASS];
__device__ float g_vB[(size_t)N_NODES * NCLASS];
__device__ float g_dinv[N_NODES];
__device__ int   g_cnt [N_NODES];
__device__ int   g_fill[N_NODES];
__device__ int   g_rowstart[N_NODES + 1];
__device__ int   g_cols[N_EDGES];
__device__ int   g_bsum[128];

// ---------------- helpers ----------------
__device__ __forceinline__ uint32_t smem_u32(const void* p) {
    uint32_t a;
    asm("{ .reg .u64 t; cvta.to.shared.u64 t, %1; cvt.u32.u64 %0, t; }" : "=r"(a) : "l"(p));
    return a;
}

__device__ __forceinline__ void mma16816(float c[4], const uint32_t a[4],
                                         uint32_t b0, uint32_t b1) {
    asm volatile(
        "mma.sync.aligned.m16n8k16.row.col.f32.bf16.bf16.f32 "
        "{%0,%1,%2,%3}, {%4,%5,%6,%7}, {%8,%9}, {%0,%1,%2,%3};"
        : "+f"(c[0]), "+f"(c[1]), "+f"(c[2]), "+f"(c[3])
        : "r"(a[0]), "r"(a[1]), "r"(a[2]), "r"(a[3]), "r"(b0), "r"(b1));
}

#define LDSM_X4(r0, r1, r2, r3, addr) \
    asm volatile("ldmatrix.sync.aligned.m8n8.x4.shared.b16 {%0,%1,%2,%3}, [%4];" \
                 : "=r"(r0), "=r"(r1), "=r"(r2), "=r"(r3) : "r"(addr))

__device__ __forceinline__ void split4(float4 v, uint2& hi, uint2& lo) {
    __nv_bfloat16 hx = __float2bfloat16(v.x);
    __nv_bfloat16 hy = __float2bfloat16(v.y);
    __nv_bfloat16 hz = __float2bfloat16(v.z);
    __nv_bfloat16 hw = __float2bfloat16(v.w);
    __nv_bfloat16 lx = __float2bfloat16(v.x - __bfloat162float(hx));
    __nv_bfloat16 ly = __float2bfloat16(v.y - __bfloat162float(hy));
    __nv_bfloat16 lz = __float2bfloat16(v.z - __bfloat162float(hz));
    __nv_bfloat16 lw = __float2bfloat16(v.w - __bfloat162float(hw));
    hi.x = ((uint32_t)__bfloat16_as_ushort(hy) << 16) | __bfloat16_as_ushort(hx);
    hi.y = ((uint32_t)__bfloat16_as_ushort(hw) << 16) | __bfloat16_as_ushort(hz);
    lo.x = ((uint32_t)__bfloat16_as_ushort(ly) << 16) | __bfloat16_as_ushort(lx);
    lo.y = ((uint32_t)__bfloat16_as_ushort(lw) << 16) | __bfloat16_as_ushort(lz);
}

__device__ __forceinline__ void split2(float2 v, uint32_t& hi, uint32_t& lo) {
    __nv_bfloat16 hx = __float2bfloat16(v.x);
    __nv_bfloat16 hy = __float2bfloat16(v.y);
    __nv_bfloat16 lx = __float2bfloat16(v.x - __bfloat162float(hx));
    __nv_bfloat16 ly = __float2bfloat16(v.y - __bfloat162float(hy));
    hi = ((uint32_t)__bfloat16_as_ushort(hy) << 16) | __bfloat16_as_ushort(hx);
    lo = ((uint32_t)__bfloat16_as_ushort(ly) << 16) | __bfloat16_as_ushort(lx);
}

// ---------------- graph preprocessing ----------------
__global__ void zero_counts() {
    int i = blockIdx.x * blockDim.x + threadIdx.x;
    if (i < N_NODES) { g_cnt[i] = 0; g_fill[i] = 0; }
}
__global__ void count_deg(const int* __restrict__ rows) {
    int e = blockIdx.x * blockDim.x + threadIdx.x;
    if (e < N_EDGES) atomicAdd(&g_cnt[rows[e]], 1);
}
__global__ void compute_dinv() {
    int i = blockIdx.x * blockDim.x + threadIdx.x;
    if (i < N_NODES) g_dinv[i] = 1.0f / (float)(g_cnt[i] + 1);
}
__global__ void scan_blocks() {
    __shared__ int s[SCAN_T];
    int t   = threadIdx.x;
    int gid = blockIdx.x * SCAN_T + t;
    int v   = (gid < N_NODES) ? g_cnt[gid] : 0;
    s[t] = v;
    __syncthreads();
    #pragma unroll
    for (int off = 1; off < SCAN_T; off <<= 1) {
        int x = (t >= off) ? s[t - off] : 0;
        __syncthreads();
        s[t] += x;
        __syncthreads();
    }
    if (gid < N_NODES) g_rowstart[gid] = s[t] - v;
    if (t == SCAN_T - 1) g_bsum[blockIdx.x] = s[t];
}
__global__ void scan_offsets() {
    if (threadIdx.x == 0 && blockIdx.x == 0) {
        int acc = 0;
        for (int i = 0; i < NBLK; i++) { int t = g_bsum[i]; g_bsum[i] = acc; acc += t; }
        g_rowstart[N_NODES] = acc;
    }
}
__global__ void scan_add() {
    int t   = threadIdx.x;
    int gid = blockIdx.x * SCAN_T + t;
    if (gid < N_NODES) g_rowstart[gid] += g_bsum[blockIdx.x];
}
__global__ void scatter_edges(const int* __restrict__ rows, const int* __restrict__ cols) {
    int e = blockIdx.x * blockDim.x + threadIdx.x;
    if (e < N_EDGES) {
        int r   = rows[e];
        int pos = g_rowstart[r] + atomicAdd(&g_fill[r], 1);
        g_cols[pos] = cols[e];
    }
}

// =============== HMMA GEMM, bf16 3-term split, K-tile 64, 2-stage pipeline ===============
#define RSB 144            // smem row stride bytes (128B data + 16B pad)

template<int BN, int RELU, int ABF16, int OUTSPLIT>
__global__ __launch_bounds__(256)
void gemm_hmma(const float* __restrict__ Af,
               const __nv_bfloat16* __restrict__ Ahi_g,
               const __nv_bfloat16* __restrict__ Alo_g,
               const float* __restrict__ W,
               const float* __restrict__ bias,
               float* __restrict__ C,
               __nv_bfloat16* __restrict__ Chi,
               __nv_bfloat16* __restrict__ Clo,
               int Nrows, int Mcols, int K)
{
    constexpr int NJ      = BN / 16;
    constexpr int ABYTES  = 128 * RSB;                   // 18432
    constexpr int BBYTES  = BN * RSB;
    constexpr int STAGE   = 2 * ABYTES + 2 * BBYTES;     // AHI|ALO|BHI|BLO
    constexpr int OFF_BS  = 2 * STAGE;
    constexpr int BLOADS  = BN / 16;                     // fp32 float4 B loads/thread

    extern __shared__ __align__(16) char sm[];

    const uint32_t smb = smem_u32(sm);
    const int tid = threadIdx.x;
    const int wid = tid >> 5;
    const int lid = tid & 31;
    const int warpM = (wid & 3) * 32;
    const int warpN = (wid >> 2) * (BN / 2);
    const int rowBase = blockIdx.y * 128;
    const int colBase = blockIdx.x * BN;
    const int NT = K / 64;

    // bias -> smem (read only in epilogue, synced by loop barriers)
    for (int i = tid; i < BN; i += 256) {
        int gc = colBase + i;
        *(float*)(sm + OFF_BS + i * 4) = (gc < Mcols) ? bias[gc] : 0.0f;
    }

    // per-lane ldmatrix address components
    const int aRow  = (lid & 7) + ((lid >> 3) & 1) * 8;
    const int aColB = (lid >> 4) * 16;
    const int bN    = ((lid >> 4) * 8) + (lid & 7);
    const int bColB = ((lid >> 3) & 1) * 16;

    const uint32_t aAddr0 = smb + (warpM + aRow) * RSB + aColB;                 // + stage*STAGE
    const uint32_t bAddr0 = smb + 2 * ABYTES + (warpN + bN) * RSB + bColB;      // + stage*STAGE

    float acc[2][NJ][4];
    #pragma unroll
    for (int i = 0; i < 2; i++)
        #pragma unroll
        for (int j = 0; j < NJ; j++)
            #pragma unroll
            for (int q = 0; q < 4; q++) acc[i][j][q] = 0.0f;

    // prefetch registers
    float4 paf[8];                 // fp32 A path
    uint4  pah[4], pal[4];         // bf16 A path
    float4 pbf[BLOADS];

    // ---- LOADREGS(t): issue global loads for k-tile t ----
    auto LOADREGS = [&](int t) {
        const int kt = t * 64;
        if (ABF16) {
            #pragma unroll
            for (int i = 0; i < 4; i++) {
                int idx = tid + i * 256;
                int row = idx >> 3;
                int c8  = idx & 7;
                int gr  = rowBase + row;
                pah[i] = make_uint4(0, 0, 0, 0);
                pal[i] = make_uint4(0, 0, 0, 0);
                if (gr < Nrows) {
                    pah[i] = *(const uint4*)(Ahi_g + (size_t)gr * K + kt + c8 * 8);
                    pal[i] = *(const uint4*)(Alo_g + (size_t)gr * K + kt + c8 * 8);
                }
            }
        } else {
            #pragma unroll
            for (int i = 0; i < 8; i++) {
                int idx = tid + i * 256;
                int row = idx >> 4;
                int c4  = idx & 15;
                int gr  = rowBase + row;
                paf[i] = make_float4(0.f, 0.f, 0.f, 0.f);
                if (gr < Nrows) paf[i] = *(const float4*)(Af + (size_t)gr * K + kt + c4 * 4);
            }
        }
        #pragma unroll
        for (int i = 0; i < BLOADS; i++) {
            int idx = tid + i * 256;
            int row = idx >> 4;
            int c4  = idx & 15;
            int gm  = colBase + row;
            pbf[i] = make_float4(0.f, 0.f, 0.f, 0.f);
            if (gm < Mcols) pbf[i] = *(const float4*)(W + (size_t)gm * K + kt + c4 * 4);
        }
    };

    // ---- STS(st): write prefetched tile into smem stage st ----
    auto STS = [&](int st) {
        char* base = sm + st * STAGE;
        if (ABF16) {
            #pragma unroll
            for (int i = 0; i < 4; i++) {
                int idx = tid + i * 256;
                int row = idx >> 3;
                int c8  = idx & 7;
                *(uint4*)(base + row * RSB + c8 * 16) = pah[i];
                *(uint4*)(base + ABYTES + row * RSB + c8 * 16) = pal[i];
            }
        } else {
            #pragma unroll
            for (int i = 0; i < 8; i++) {
                int idx = tid + i * 256;
                int row = idx >> 4;
                int c4  = idx & 15;
                uint2 hi, lo; split4(paf[i], hi, lo);
                *(uint2*)(base + row * RSB + c4 * 8) = hi;
                *(uint2*)(base + ABYTES + row * RSB + c4 * 8) = lo;
            }
        }
        #pragma unroll
        for (int i = 0; i < BLOADS; i++) {
            int idx = tid + i * 256;
            int row = idx >> 4;
            int c4  = idx & 15;
            uint2 hi, lo; split4(pbf[i], hi, lo);
            *(uint2*)(base + 2 * ABYTES + row * RSB + c4 * 8) = hi;
            *(uint2*)(base + 2 * ABYTES + BBYTES + row * RSB + c4 * 8) = lo;
        }
    };

    // ---- MMA(st): consume smem stage st ----
    auto MMA = [&](int st) {
        const uint32_t aA = aAddr0 + st * STAGE;
        const uint32_t bA = bAddr0 + st * STAGE;
        #pragma unroll
        for (int ks = 0; ks < 4; ks++) {
            const uint32_t kOff = ks * 32;
            uint32_t ah[2][4], al[2][4];
            #pragma unroll
            for (int i = 0; i < 2; i++) {
                uint32_t aa = aA + i * 16 * RSB + kOff;
                LDSM_X4(ah[i][0], ah[i][1], ah[i][2], ah[i][3], aa);
                LDSM_X4(al[i][0], al[i][1], al[i][2], al[i][3], aa + ABYTES);
            }
            #pragma unroll
            for (int jp = 0; jp < NJ / 2; jp++) {
                uint32_t bb = bA + jp * 16 * RSB + kOff;
                uint32_t bh0, bh1, bh2, bh3, bl0, bl1, bl2, bl3;
                LDSM_X4(bh0, bh1, bh2, bh3, bb);
                LDSM_X4(bl0, bl1, bl2, bl3, bb + BBYTES);
                #pragma unroll
                for (int i = 0; i < 2; i++) {
                    mma16816(acc[i][2 * jp],     ah[i], bh0, bh1);
                    mma16816(acc[i][2 * jp],     ah[i], bl0, bl1);
                    mma16816(acc[i][2 * jp],     al[i], bh0, bh1);
                    mma16816(acc[i][2 * jp + 1], ah[i], bh2, bh3);
                    mma16816(acc[i][2 * jp + 1], ah[i], bl2, bl3);
                    mma16816(acc[i][2 * jp + 1], al[i], bh2, bh3);
                }
            }
        }
    };

    // ---- pipelined mainloop: one sync per k-tile ----
    LOADREGS(0);
    for (int t = 0; t < NT; t++) {
        STS(t & 1);
        __syncthreads();
        if (t + 1 < NT) LOADREGS(t + 1);
        MMA(t & 1);
    }

    // ---- epilogue ----
    const int rBase = rowBase + warpM + (lid >> 2);
    const int cOff  = warpN + (lid & 3) * 2;
    #pragma unroll
    for (int i = 0; i < 2; i++) {
        #pragma unroll
        for (int j = 0; j < NJ; j++) {
            int cl = cOff + j * 8;
            int gc = colBase + cl;
            if (gc >= Mcols) continue;
            float2 bb = *(const float2*)(sm + OFF_BS + cl * 4);
            int r0 = rBase + i * 16;
            int r1 = r0 + 8;
            float2 v0, v1;
            v0.x = acc[i][j][0] + bb.x; v0.y = acc[i][j][1] + bb.y;
            v1.x = acc[i][j][2] + bb.x; v1.y = acc[i][j][3] + bb.y;
            if (RELU) {
                v0.x = fmaxf(v0.x, 0.f); v0.y = fmaxf(v0.y, 0.f);
                v1.x = fmaxf(v1.x, 0.f); v1.y = fmaxf(v1.y, 0.f);
            }
            if (OUTSPLIT) {
                uint32_t h0, l0, h1v, l1;
                split2(v0, h0, l0);
                split2(v1, h1v, l1);
                if (r0 < Nrows) {
                    *(uint32_t*)(Chi + (size_t)r0 * Mcols + gc) = h0;
                    *(uint32_t*)(Clo + (size_t)r0 * Mcols + gc) = l0;
                }
                if (r1 < Nrows) {
                    *(uint32_t*)(Chi + (size_t)r1 * Mcols + gc) = h1v;
                    *(uint32_t*)(Clo + (size_t)r1 * Mcols + gc) = l1;
                }
            } else {
                if (r0 < Nrows) *(float2*)(C + (size_t)r0 * Mcols + gc) = v0;
                if (r1 < Nrows) *(float2*)(C + (size_t)r1 * Mcols + gc) = v1;
            }
        }
    }
}

// ---------------- SpMM power-iteration step ----------------
__global__ __launch_bounds__(320)
void spmm_step(const float4* __restrict__ v4, const float4* __restrict__ h4,
               float4* __restrict__ out4)
{
    int t = blockIdx.x * 320 + threadIdx.x;
    int r = t / NF4;
    int f = t - r * NF4;
    if (r >= N_NODES) return;

    int s = g_rowstart[r];
    int e = g_rowstart[r + 1];

    float ax = 0.f, ay = 0.f, az = 0.f, aw = 0.f;
    int i = s;
    for (; i + 4 <= e; i += 4) {
        int c0 = g_cols[i + 0], c1 = g_cols[i + 1];
        int c2 = g_cols[i + 2], c3 = g_cols[i + 3];
        float4 p0 = __ldg(v4 + (size_t)c0 * NF4 + f);
        float4 p1 = __ldg(v4 + (size_t)c1 * NF4 + f);
        float4 p2 = __ldg(v4 + (size_t)c2 * NF4 + f);
        float4 p3 = __ldg(v4 + (size_t)c3 * NF4 + f);
        ax += (p0.x + p1.x) + (p2.x + p3.x);
        ay += (p0.y + p1.y) + (p2.y + p3.y);
        az += (p0.z + p1.z) + (p2.z + p3.z);
        aw += (p0.w + p1.w) + (p2.w + p3.w);
    }
    for (; i < e; i++) {
        int c = g_cols[i];
        float4 p = __ldg(v4 + (size_t)c * NF4 + f);
        ax += p.x; ay += p.y; az += p.z; aw += p.w;
    }

    float4 vr = __ldg(v4 + (size_t)r * NF4 + f);
    float4 hr = __ldg(h4 + (size_t)r * NF4 + f);
    float  w  = 0.5f * g_dinv[r];

    float4 o;
    o.x = w * (ax + vr.x) + 0.5f * hr.x;
    o.y = w * (ay + vr.y) + 0.5f * hr.y;
    o.z = w * (az + vr.z) + 0.5f * hr.z;
    o.w = w * (aw + vr.w) + 0.5f * hr.w;
    out4[(size_t)r * NF4 + f] = o;
}

// ---------------- host ----------------
extern "C" void kernel_launch(void* const* d_in, const int* in_sizes, int n_in,
                              void* d_out, int out_size)
{
    const float* x  = (const float*)d_in[0];
    const int*   ei = (const int*)  d_in[1];
    const float* W1 = (const float*)d_in[2];
    const float* b1 = (const float*)d_in[3];
    const float* W2 = (const float*)d_in[4];
    const float* b2 = (const float*)d_in[5];
    const float* W3 = (const float*)d_in[6];
    const float* b3 = (const float*)d_in[7];
    float* out = (float*)d_out;

    const int* rows = ei;
    const int* cols = ei + N_EDGES;

    void *p;
    float *h1, *h2, *h, *vA, *vB;
    cudaGetSymbolAddress(&p, g_h1); h1 = (float*)p;
    cudaGetSymbolAddress(&p, g_h2); h2 = (float*)p;
    cudaGetSymbolAddress(&p, g_h);  h  = (float*)p;
    cudaGetSymbolAddress(&p, g_vA); vA = (float*)p;
    cudaGetSymbolAddress(&p, g_vB); vB = (float*)p;

    __nv_bfloat16* h1hi = (__nv_bfloat16*)h1;
    __nv_bfloat16* h1lo = h1hi + (size_t)N_NODES * NHID;
    __nv_bfloat16* h2hi = (__nv_bfloat16*)h2;
    __nv_bfloat16* h2lo = h2hi + (size_t)N_NODES * NHID;

    // ---- CSR build ----
    zero_counts <<<(N_NODES + 255) / 256, 256>>>();
    count_deg   <<<(N_EDGES + 255) / 256, 256>>>(rows);
    compute_dinv<<<(N_NODES + 255) / 256, 256>>>();
    scan_blocks <<<NBLK, SCAN_T>>>();
    scan_offsets<<<1, 32>>>();
    scan_add    <<<NBLK, SCAN_T>>>();
    scatter_edges<<<(N_EDGES + 255) / 256, 256>>>(rows, cols);

    // ---- MLP via pipelined HMMA bf16 3-term split ----
    const int STG128 = 2 * (128 * RSB) + 2 * (128 * RSB);   // 73728
    const int STG64  = 2 * (128 * RSB) + 2 * (64 * RSB);    // 55296
    const int SMEM_128 = 2 * STG128 + 128 * 4;              // 147968
    const int SMEM_64  = 2 * STG64 + 64 * 4;                // 110848
    cudaFuncSetAttribute((const void*)gemm_hmma<128, 1, 0, 1>,
                         cudaFuncAttributeMaxDynamicSharedMemorySize, SMEM_128);
    cudaFuncSetAttribute((const void*)gemm_hmma<128, 1, 1, 1>,
                         cudaFuncAttributeMaxDynamicSharedMemorySize, SMEM_128);
    cudaFuncSetAttribute((const void*)gemm_hmma<64, 0, 1, 0>,
                         cudaFuncAttributeMaxDynamicSharedMemorySize, SMEM_64);

    const int MG = (N_NODES + 127) / 128;   // 782
    gemm_hmma<128, 1, 0, 1><<<dim3(2, MG), 256, SMEM_128>>>(
        x, nullptr, nullptr, W1, b1, nullptr, h1hi, h1lo, N_NODES, NHID, NFEAT);
    gemm_hmma<128, 1, 1, 1><<<dim3(2, MG), 256, SMEM_128>>>(
        nullptr, h1hi, h1lo, W2, b2, nullptr, h2hi, h2lo, N_NODES, NHID, NHID);
    gemm_hmma<64, 0, 1, 0><<<dim3(1, MG), 256, SMEM_64>>>(
        nullptr, h2hi, h2lo, W3, b3, h, nullptr, nullptr, N_NODES, NCLASS, NHID);

    // ---- 10 power iterations ----
    const int SP_G = (N_NODES * NF4 + 319) / 320;
    const float* src = h;
    for (int it = 0; it < 10; it++) {
        float* dst = (it == 9) ? out : ((it & 1) ? vB : vA);
        spmm_step<<<SP_G, 320>>>((const float4*)src, (const float4*)h, (float4*)dst);
        src = dst;
    }
}

// round 9
// speedup vs baseline: 1.1641x; 1.1641x over previous
#include <cuda_runtime.h>
#include <cuda_bf16.h>
#include <cstdint>

#define N_NODES 100000
#define N_EDGES 1600000
#define NFEAT   512
#define NHID    256
#define NCLASS  40
#define NF4     (NCLASS / 4)

#define SCAN_T  1024
#define NBLK    ((N_NODES + SCAN_T - 1) / SCAN_T)   // 98

// ---------------- scratch (static device globals; no allocation) ----------------
__device__ float g_h1[(size_t)N_NODES * NHID];   // holds bf16 hi|lo of h1 (aliased)
__device__ float g_h2[(size_t)N_NODES * NHID];   // holds bf16 hi|lo of h2 (aliased)
__device__ float g_h [(size_t)N_NODES * NCLASS];
__device__ float g_vA[(size_t)N_NODES * NCLASS];
__device__ float g_vB[(size_t)N_NODES * NCLASS];
__device__ float g_dinv[N_NODES];
__device__ int   g_cnt [N_NODES];
__device__ int   g_fill[N_NODES];
__device__ int   g_rowstart[N_NODES + 1];
__device__ int   g_cols[N_EDGES];
__device__ int   g_bsum[128];
// pre-split weights (bf16 hi/lo), 16B-aligned
__device__ __align__(16) __nv_bfloat16 g_w1hi[NHID * NFEAT];
__device__ __align__(16) __nv_bfloat16 g_w1lo[NHID * NFEAT];
__device__ __align__(16) __nv_bfloat16 g_w2hi[NHID * NHID];
__device__ __align__(16) __nv_bfloat16 g_w2lo[NHID * NHID];
__device__ __align__(16) __nv_bfloat16 g_w3hi[NCLASS * NHID];
__device__ __align__(16) __nv_bfloat16 g_w3lo[NCLASS * NHID];

// ---------------- helpers ----------------
__device__ __forceinline__ uint32_t smem_u32(const void* p) {
    uint32_t a;
    asm("{ .reg .u64 t; cvta.to.shared.u64 t, %1; cvt.u32.u64 %0, t; }" : "=r"(a) : "l"(p));
    return a;
}

__device__ __forceinline__ void mma16816(float c[4], const uint32_t a[4],
                                         uint32_t b0, uint32_t b1) {
    asm volatile(
        "mma.sync.aligned.m16n8k16.row.col.f32.bf16.bf16.f32 "
        "{%0,%1,%2,%3}, {%4,%5,%6,%7}, {%8,%9}, {%0,%1,%2,%3};"
        : "+f"(c[0]), "+f"(c[1]), "+f"(c[2]), "+f"(c[3])
        : "r"(a[0]), "r"(a[1]), "r"(a[2]), "r"(a[3]), "r"(b0), "r"(b1));
}

#define LDSM_X4(r0, r1, r2, r3, addr) \
    asm volatile("ldmatrix.sync.aligned.m8n8.x4.shared.b16 {%0,%1,%2,%3}, [%4];" \
                 : "=r"(r0), "=r"(r1), "=r"(r2), "=r"(r3) : "r"(addr))

__device__ __forceinline__ void cp16(uint32_t dst, const void* src, uint32_t bytes) {
    asm volatile("cp.async.cg.shared.global [%0], [%1], 16, %2;"
                 :: "r"(dst), "l"(src), "r"(bytes));
}
#define CP_COMMIT() asm volatile("cp.async.commit_group;" ::: "memory")
#define CP_WAIT(n)  asm volatile("cp.async.wait_group %0;" :: "n"(n) : "memory")

__device__ __forceinline__ void split4(float4 v, uint2& hi, uint2& lo) {
    __nv_bfloat16 hx = __float2bfloat16(v.x);
    __nv_bfloat16 hy = __float2bfloat16(v.y);
    __nv_bfloat16 hz = __float2bfloat16(v.z);
    __nv_bfloat16 hw = __float2bfloat16(v.w);
    __nv_bfloat16 lx = __float2bfloat16(v.x - __bfloat162float(hx));
    __nv_bfloat16 ly = __float2bfloat16(v.y - __bfloat162float(hy));
    __nv_bfloat16 lz = __float2bfloat16(v.z - __bfloat162float(hz));
    __nv_bfloat16 lw = __float2bfloat16(v.w - __bfloat162float(hw));
    hi.x = ((uint32_t)__bfloat16_as_ushort(hy) << 16) | __bfloat16_as_ushort(hx);
    hi.y = ((uint32_t)__bfloat16_as_ushort(hw) << 16) | __bfloat16_as_ushort(hz);
    lo.x = ((uint32_t)__bfloat16_as_ushort(ly) << 16) | __bfloat16_as_ushort(lx);
    lo.y = ((uint32_t)__bfloat16_as_ushort(lw) << 16) | __bfloat16_as_ushort(lz);
}

__device__ __forceinline__ void split2(float2 v, uint32_t& hi, uint32_t& lo) {
    __nv_bfloat16 hx = __float2bfloat16(v.x);
    __nv_bfloat16 hy = __float2bfloat16(v.y);
    __nv_bfloat16 lx = __float2bfloat16(v.x - __bfloat162float(hx));
    __nv_bfloat16 ly = __float2bfloat16(v.y - __bfloat162float(hy));
    hi = ((uint32_t)__bfloat16_as_ushort(hy) << 16) | __bfloat16_as_ushort(hx);
    lo = ((uint32_t)__bfloat16_as_ushort(ly) << 16) | __bfloat16_as_ushort(lx);
}

// ---------------- graph preprocessing ----------------
__global__ void zero_counts() {
    int i = blockIdx.x * blockDim.x + threadIdx.x;
    if (i < N_NODES) { g_cnt[i] = 0; g_fill[i] = 0; }
}
__global__ void count_deg(const int* __restrict__ rows) {
    int e = blockIdx.x * blockDim.x + threadIdx.x;
    if (e < N_EDGES) atomicAdd(&g_cnt[rows[e]], 1);
}
__global__ void compute_dinv() {
    int i = blockIdx.x * blockDim.x + threadIdx.x;
    if (i < N_NODES) g_dinv[i] = 1.0f / (float)(g_cnt[i] + 1);
}
__global__ void scan_blocks() {
    __shared__ int s[SCAN_T];
    int t   = threadIdx.x;
    int gid = blockIdx.x * SCAN_T + t;
    int v   = (gid < N_NODES) ? g_cnt[gid] : 0;
    s[t] = v;
    __syncthreads();
    #pragma unroll
    for (int off = 1; off < SCAN_T; off <<= 1) {
        int x = (t >= off) ? s[t - off] : 0;
        __syncthreads();
        s[t] += x;
        __syncthreads();
    }
    if (gid < N_NODES) g_rowstart[gid] = s[t] - v;
    if (t == SCAN_T - 1) g_bsum[blockIdx.x] = s[t];
}
__global__ void scan_offsets() {
    if (threadIdx.x == 0 && blockIdx.x == 0) {
        int acc = 0;
        for (int i = 0; i < NBLK; i++) { int t = g_bsum[i]; g_bsum[i] = acc; acc += t; }
        g_rowstart[N_NODES] = acc;
    }
}
__global__ void scan_add() {
    int t   = threadIdx.x;
    int gid = blockIdx.x * SCAN_T + t;
    if (gid < N_NODES) g_rowstart[gid] += g_bsum[blockIdx.x];
}
__global__ void scatter_edges(const int* __restrict__ rows, const int* __restrict__ cols) {
    int e = blockIdx.x * blockDim.x + threadIdx.x;
    if (e < N_EDGES) {
        int r   = rows[e];
        int pos = g_rowstart[r] + atomicAdd(&g_fill[r], 1);
        g_cols[pos] = cols[e];
    }
}
__global__ void split_w(const float* __restrict__ src, __nv_bfloat16* __restrict__ hi,
                        __nv_bfloat16* __restrict__ lo, int n) {
    int i = blockIdx.x * 256 + threadIdx.x;
    if (i < n) {
        float v = src[i];
        __nv_bfloat16 h = __float2bfloat16(v);
        hi[i] = h;
        lo[i] = __float2bfloat16(v - __bfloat162float(h));
    }
}

// ====== HMMA GEMM, bf16 3-term split, K-tile 32, 2-stage cp.async pipeline ======
#define RSB 80             // smem row stride bytes (64B data + 16B pad)

template<int BN, int RELU, int ABF16, int OUTSPLIT>
__global__ __launch_bounds__(256, 2)
void gemm_hmma(const float* __restrict__ Af,
               const __nv_bfloat16* __restrict__ Ahi_g,
               const __nv_bfloat16* __restrict__ Alo_g,
               const __nv_bfloat16* __restrict__ Whi_g,
               const __nv_bfloat16* __restrict__ Wlo_g,
               const float* __restrict__ bias,
               float* __restrict__ C,
               __nv_bfloat16* __restrict__ Chi,
               __nv_bfloat16* __restrict__ Clo,
               int Nrows, int Mcols, int K)
{
    constexpr int NJ      = BN / 16;
    constexpr int ABYTES  = 128 * RSB;                   // 10240
    constexpr int BBYTES  = BN * RSB;
    constexpr int STAGE   = 2 * ABYTES + 2 * BBYTES;     // AHI|ALO|BHI|BLO
    constexpr int OFF_BS  = 2 * STAGE;
    constexpr int BCHUNKS = BN / 64;                     // cp.async 16B iters for B

    extern __shared__ __align__(16) char sm[];

    const uint32_t smb = smem_u32(sm);
    const int tid = threadIdx.x;
    const int wid = tid >> 5;
    const int lid = tid & 31;
    const int warpM = (wid & 3) * 32;
    const int warpN = (wid >> 2) * (BN / 2);
    const int rowBase = blockIdx.y * 128;
    const int colBase = blockIdx.x * BN;
    const int NT = K / 32;

    // bias -> smem
    for (int i = tid; i < BN; i += 256) {
        int gc = colBase + i;
        *(float*)(sm + OFF_BS + i * 4) = (gc < Mcols) ? bias[gc] : 0.0f;
    }

    // per-lane ldmatrix address components
    const int aRow  = (lid & 7) + ((lid >> 3) & 1) * 8;
    const int aColB = (lid >> 4) * 16;
    const int bN    = ((lid >> 4) * 8) + (lid & 7);
    const int bColB = ((lid >> 3) & 1) * 16;

    const uint32_t aAddr0 = smb + (warpM + aRow) * RSB + aColB;
    const uint32_t bAddr0 = smb + 2 * ABYTES + (warpN + bN) * RSB + bColB;

    float acc[2][NJ][4];
    #pragma unroll
    for (int i = 0; i < 2; i++)
        #pragma unroll
        for (int j = 0; j < NJ; j++)
            #pragma unroll
            for (int q = 0; q < 4; q++) acc[i][j][q] = 0.0f;

    float4 paf[4];   // fp32-A prefetch (ABF16=0 only)

    // cp.async A (bf16 path): 128x32 hi + lo, 2 chunks each per thread
    auto cpA = [&](int t, int st) {
        const int kt = t * 32;
        char* base = sm + st * STAGE;
        #pragma unroll
        for (int i = 0; i < 2; i++) {
            int idx = tid + i * 256;
            int row = idx >> 2;
            int c   = idx & 3;
            int gr  = rowBase + row;
            uint32_t sz = (gr < Nrows) ? 16u : 0u;
            int gra = (gr < Nrows) ? gr : 0;
            uint32_t so = smem_u32(base + row * RSB + c * 16);
            cp16(so,          Ahi_g + (size_t)gra * K + kt + c * 8, sz);
            cp16(so + ABYTES, Alo_g + (size_t)gra * K + kt + c * 8, sz);
        }
    };
    // cp.async B: BN x 32 hi + lo
    auto cpB = [&](int t, int st) {
        const int kt = t * 32;
        char* base = sm + st * STAGE + 2 * ABYTES;
        #pragma unroll
        for (int i = 0; i < BCHUNKS; i++) {
            int idx = tid + i * 256;
            int row = idx >> 2;
            int c   = idx & 3;
            int gm  = colBase + row;
            uint32_t sz = (gm < Mcols) ? 16u : 0u;
            int gma = (gm < Mcols) ? gm : 0;
            uint32_t so = smem_u32(base + row * RSB + c * 16);
            cp16(so,          Whi_g + (size_t)gma * K + kt + c * 8, sz);
            cp16(so + BBYTES, Wlo_g + (size_t)gma * K + kt + c * 8, sz);
        }
    };
    // fp32 A prefetch to regs (ABF16=0): 128x32 fp32, 4 float4/thread
    auto ldA = [&](int t) {
        const int kt = t * 32;
        #pragma unroll
        for (int i = 0; i < 4; i++) {
            int idx = tid + i * 256;
            int row = idx >> 3;
            int c4  = idx & 7;
            int gr  = rowBase + row;
            paf[i] = make_float4(0.f, 0.f, 0.f, 0.f);
            if (gr < Nrows) paf[i] = *(const float4*)(Af + (size_t)gr * K + kt + c4 * 4);
        }
    };
    auto stsA = [&](int st) {
        char* base = sm + st * STAGE;
        #pragma unroll
        for (int i = 0; i < 4; i++) {
            int idx = tid + i * 256;
            int row = idx >> 3;
            int c4  = idx & 7;
            uint2 hi, lo; split4(paf[i], hi, lo);
            *(uint2*)(base + row * RSB + c4 * 8) = hi;
            *(uint2*)(base + ABYTES + row * RSB + c4 * 8) = lo;
        }
    };

    auto MMA = [&](int st) {
        const uint32_t aA = aAddr0 + st * STAGE;
        const uint32_t bA = bAddr0 + st * STAGE;
        #pragma unroll
        for (int ks = 0; ks < 2; ks++) {
            const uint32_t kOff = ks * 32;
            uint32_t ah[2][4], al[2][4];
            #pragma unroll
            for (int i = 0; i < 2; i++) {
                uint32_t aa = aA + i * 16 * RSB + kOff;
                LDSM_X4(ah[i][0], ah[i][1], ah[i][2], ah[i][3], aa);
                LDSM_X4(al[i][0], al[i][1], al[i][2], al[i][3], aa + ABYTES);
            }
            #pragma unroll
            for (int jp = 0; jp < NJ / 2; jp++) {
                uint32_t bb = bA + jp * 16 * RSB + kOff;
                uint32_t bh0, bh1, bh2, bh3, bl0, bl1, bl2, bl3;
                LDSM_X4(bh0, bh1, bh2, bh3, bb);
                LDSM_X4(bl0, bl1, bl2, bl3, bb + BBYTES);
                #pragma unroll
                for (int i = 0; i < 2; i++) {
                    mma16816(acc[i][2 * jp],     ah[i], bh0, bh1);
                    mma16816(acc[i][2 * jp],     ah[i], bl0, bl1);
                    mma16816(acc[i][2 * jp],     al[i], bh0, bh1);
                    mma16816(acc[i][2 * jp + 1], ah[i], bh2, bh3);
                    mma16816(acc[i][2 * jp + 1], ah[i], bl2, bl3);
                    mma16816(acc[i][2 * jp + 1], al[i], bh2, bh3);
                }
            }
        }
    };

    // ---- prologue: stage 0 in flight ----
    if (ABF16) cpA(0, 0); else ldA(0);
    cpB(0, 0);
    CP_COMMIT();

    // ---- mainloop ----
    for (int t = 0; t < NT; t++) {
        const int st = t & 1;
        if (!ABF16) stsA(st);                 // A(t) regs -> smem
        if (t + 1 < NT) {
            const int sn = (t + 1) & 1;
            if (ABF16) cpA(t + 1, sn); else ldA(t + 1);
            cpB(t + 1, sn);
        }
        CP_COMMIT();
        if (t + 1 < NT) { CP_WAIT(1); } else { CP_WAIT(0); }
        __syncthreads();
        MMA(st);
        __syncthreads();
    }

    // ---- epilogue ----
    const int rBase = rowBase + warpM + (lid >> 2);
    const int cOff  = warpN + (lid & 3) * 2;
    #pragma unroll
    for (int i = 0; i < 2; i++) {
        #pragma unroll
        for (int j = 0; j < NJ; j++) {
            int cl = cOff + j * 8;
            int gc = colBase + cl;
            if (gc >= Mcols) continue;
            float2 bb = *(const float2*)(sm + OFF_BS + cl * 4);
            int r0 = rBase + i * 16;
            int r1 = r0 + 8;
            float2 v0, v1;
            v0.x = acc[i][j][0] + bb.x; v0.y = acc[i][j][1] + bb.y;
            v1.x = acc[i][j][2] + bb.x; v1.y = acc[i][j][3] + bb.y;
            if (RELU) {
                v0.x = fmaxf(v0.x, 0.f); v0.y = fmaxf(v0.y, 0.f);
                v1.x = fmaxf(v1.x, 0.f); v1.y = fmaxf(v1.y, 0.f);
            }
            if (OUTSPLIT) {
                uint32_t h0, l0, h1v, l1;
                split2(v0, h0, l0);
                split2(v1, h1v, l1);
                if (r0 < Nrows) {
                    *(uint32_t*)(Chi + (size_t)r0 * Mcols + gc) = h0;
                    *(uint32_t*)(Clo + (size_t)r0 * Mcols + gc) = l0;
                }
                if (r1 < Nrows) {
                    *(uint32_t*)(Chi + (size_t)r1 * Mcols + gc) = h1v;
                    *(uint32_t*)(Clo + (size_t)r1 * Mcols + gc) = l1;
                }
            } else {
                if (r0 < Nrows) *(float2*)(C + (size_t)r0 * Mcols + gc) = v0;
                if (r1 < Nrows) *(float2*)(C + (size_t)r1 * Mcols + gc) = v1;
            }
        }
    }
}

// ---------------- SpMM power-iteration step ----------------
__global__ __launch_bounds__(320)
void spmm_step(const float4* __restrict__ v4, const float4* __restrict__ h4,
               float4* __restrict__ out4)
{
    int t = blockIdx.x * 320 + threadIdx.x;
    int r = t / NF4;
    int f = t - r * NF4;
    if (r >= N_NODES) return;

    int s = g_rowstart[r];
    int e = g_rowstart[r + 1];

    float ax = 0.f, ay = 0.f, az = 0.f, aw = 0.f;
    int i = s;
    for (; i + 4 <= e; i += 4) {
        int c0 = g_cols[i + 0], c1 = g_cols[i + 1];
        int c2 = g_cols[i + 2], c3 = g_cols[i + 3];
        float4 p0 = __ldg(v4 + (size_t)c0 * NF4 + f);
        float4 p1 = __ldg(v4 + (size_t)c1 * NF4 + f);
        float4 p2 = __ldg(v4 + (size_t)c2 * NF4 + f);
        float4 p3 = __ldg(v4 + (size_t)c3 * NF4 + f);
        ax += (p0.x + p1.x) + (p2.x + p3.x);
        ay += (p0.y + p1.y) + (p2.y + p3.y);
        az += (p0.z + p1.z) + (p2.z + p3.z);
        aw += (p0.w + p1.w) + (p2.w + p3.w);
    }
    for (; i < e; i++) {
        int c = g_cols[i];
        float4 p = __ldg(v4 + (size_t)c * NF4 + f);
        ax += p.x; ay += p.y; az += p.z; aw += p.w;
    }

    float4 vr = __ldg(v4 + (size_t)r * NF4 + f);
    float4 hr = __ldg(h4 + (size_t)r * NF4 + f);
    float  w  = 0.5f * g_dinv[r];

    float4 o;
    o.x = w * (ax + vr.x) + 0.5f * hr.x;
    o.y = w * (ay + vr.y) + 0.5f * hr.y;
    o.z = w * (az + vr.z) + 0.5f * hr.z;
    o.w = w * (aw + vr.w) + 0.5f * hr.w;
    out4[(size_t)r * NF4 + f] = o;
}

// ---------------- host ----------------
extern "C" void kernel_launch(void* const* d_in, const int* in_sizes, int n_in,
                              void* d_out, int out_size)
{
    const float* x  = (const float*)d_in[0];
    const int*   ei = (const int*)  d_in[1];
    const float* W1 = (const float*)d_in[2];
    const float* b1 = (const float*)d_in[3];
    const float* W2 = (const float*)d_in[4];
    const float* b2 = (const float*)d_in[5];
    const float* W3 = (const float*)d_in[6];
    const float* b3 = (const float*)d_in[7];
    float* out = (float*)d_out;

    const int* rows = ei;
    const int* cols = ei + N_EDGES;

    void *p;
    float *h1, *h2, *h, *vA, *vB;
    __nv_bfloat16 *w1hi, *w1lo, *w2hi, *w2lo, *w3hi, *w3lo;
    cudaGetSymbolAddress(&p, g_h1);   h1 = (float*)p;
    cudaGetSymbolAddress(&p, g_h2);   h2 = (float*)p;
    cudaGetSymbolAddress(&p, g_h);    h  = (float*)p;
    cudaGetSymbolAddress(&p, g_vA);   vA = (float*)p;
    cudaGetSymbolAddress(&p, g_vB);   vB = (float*)p;
    cudaGetSymbolAddress(&p, g_w1hi); w1hi = (__nv_bfloat16*)p;
    cudaGetSymbolAddress(&p, g_w1lo); w1lo = (__nv_bfloat16*)p;
    cudaGetSymbolAddress(&p, g_w2hi); w2hi = (__nv_bfloat16*)p;
    cudaGetSymbolAddress(&p, g_w2lo); w2lo = (__nv_bfloat16*)p;
    cudaGetSymbolAddress(&p, g_w3hi); w3hi = (__nv_bfloat16*)p;
    cudaGetSymbolAddress(&p, g_w3lo); w3lo = (__nv_bfloat16*)p;

    __nv_bfloat16* h1hi = (__nv_bfloat16*)h1;
    __nv_bfloat16* h1lo = h1hi + (size_t)N_NODES * NHID;
    __nv_bfloat16* h2hi = (__nv_bfloat16*)h2;
    __nv_bfloat16* h2lo = h2hi + (size_t)N_NODES * NHID;

    // ---- CSR build + weight pre-split ----
    zero_counts <<<(N_NODES + 255) / 256, 256>>>();
    count_deg   <<<(N_EDGES + 255) / 256, 256>>>(rows);
    compute_dinv<<<(N_NODES + 255) / 256, 256>>>();
    scan_blocks <<<NBLK, SCAN_T>>>();
    scan_offsets<<<1, 32>>>();
    scan_add    <<<NBLK, SCAN_T>>>();
    scatter_edges<<<(N_EDGES + 255) / 256, 256>>>(rows, cols);
    split_w<<<(NHID * NFEAT  + 255) / 256, 256>>>(W1, w1hi, w1lo, NHID * NFEAT);
    split_w<<<(NHID * NHID   + 255) / 256, 256>>>(W2, w2hi, w2lo, NHID * NHID);
    split_w<<<(NCLASS * NHID + 255) / 256, 256>>>(W3, w3hi, w3lo, NCLASS * NHID);

    // ---- MLP via cp.async pipelined HMMA (bf16 3-term split) ----
    const int STG128 = 2 * (128 * RSB) + 2 * (128 * RSB);   // 40960
    const int STG64  = 2 * (128 * RSB) + 2 * (64 * RSB);    // 30720
    const int SMEM_128 = 2 * STG128 + 128 * 4;              // 82432
    const int SMEM_64  = 2 * STG64 + 64 * 4;                // 61696
    cudaFuncSetAttribute((const void*)gemm_hmma<128, 1, 0, 1>,
                         cudaFuncAttributeMaxDynamicSharedMemorySize, SMEM_128);
    cudaFuncSetAttribute((const void*)gemm_hmma<128, 1, 1, 1>,
                         cudaFuncAttributeMaxDynamicSharedMemorySize, SMEM_128);
    cudaFuncSetAttribute((const void*)gemm_hmma<64, 0, 1, 0>,
                         cudaFuncAttributeMaxDynamicSharedMemorySize, SMEM_64);

    const int MG = (N_NODES + 127) / 128;   // 782
    gemm_hmma<128, 1, 0, 1><<<dim3(2, MG), 256, SMEM_128>>>(
        x, nullptr, nullptr, w1hi, w1lo, b1, nullptr, h1hi, h1lo, N_NODES, NHID, NFEAT);
    gemm_hmma<128, 1, 1, 1><<<dim3(2, MG), 256, SMEM_128>>>(
        nullptr, h1hi, h1lo, w2hi, w2lo, b2, nullptr, h2hi, h2lo, N_NODES, NHID, NHID);
    gemm_hmma<64, 0, 1, 0><<<dim3(1, MG), 256, SMEM_64>>>(
        nullptr, h2hi, h2lo, w3hi, w3lo, b3, h, nullptr, nullptr, N_NODES, NCLASS, NHID);

    // ---- 10 power iterations ----
    const int SP_G = (N_NODES * NF4 + 319) / 320;
    const float* src = h;
    for (int it = 0; it < 10; it++) {
        float* dst = (it == 9) ? out : ((it & 1) ? vB : vA);
        spmm_step<<<SP_G, 320>>>((const float4*)src, (const float4*)h, (float4*)dst);
        src = dst;
    }
}

// round 10
// speedup vs baseline: 1.2035x; 1.0339x over previous
#include <cuda_runtime.h>
#include <cuda_bf16.h>
#include <cstdint>

#define N_NODES 100000
#define N_EDGES 1600000
#define NFEAT   512
#define NHID    256
#define NCLASS  40
#define NF4     (NCLASS / 4)

#define SCAN_T  1024
#define NBLK    ((N_NODES + SCAN_T - 1) / SCAN_T)   // 98

// ---------------- scratch (static device globals; no allocation) ----------------
__device__ float g_h1[(size_t)N_NODES * NHID];   // holds bf16 hi|lo of h1 (aliased)
__device__ float g_h2[(size_t)N_NODES * NHID];   // holds bf16 hi|lo of h2 (aliased)
__device__ float g_h [(size_t)N_NODES * NCLASS];
__device__ float g_vA[(size_t)N_NODES * NCLASS];
__device__ float g_vB[(size_t)N_NODES * NCLASS];
__device__ float g_dinv[N_NODES];
__device__ int   g_cnt [N_NODES];
__device__ int   g_fill[N_NODES];
__device__ int   g_rowstart[N_NODES + 1];
__device__ int   g_cols[N_EDGES];
__device__ int   g_bsum[128];
// pre-split weights (bf16 hi/lo), 16B-aligned
__device__ __align__(16) __nv_bfloat16 g_w1hi[NHID * NFEAT];
__device__ __align__(16) __nv_bfloat16 g_w1lo[NHID * NFEAT];
__device__ __align__(16) __nv_bfloat16 g_w2hi[NHID * NHID];
__device__ __align__(16) __nv_bfloat16 g_w2lo[NHID * NHID];
__device__ __align__(16) __nv_bfloat16 g_w3hi[NCLASS * NHID];
__device__ __align__(16) __nv_bfloat16 g_w3lo[NCLASS * NHID];

// ---------------- helpers ----------------
__device__ __forceinline__ uint32_t smem_u32(const void* p) {
    uint32_t a;
    asm("{ .reg .u64 t; cvta.to.shared.u64 t, %1; cvt.u32.u64 %0, t; }" : "=r"(a) : "l"(p));
    return a;
}

__device__ __forceinline__ void mma16816(float c[4], const uint32_t a[4],
                                         uint32_t b0, uint32_t b1) {
    asm volatile(
        "mma.sync.aligned.m16n8k16.row.col.f32.bf16.bf16.f32 "
        "{%0,%1,%2,%3}, {%4,%5,%6,%7}, {%8,%9}, {%0,%1,%2,%3};"
        : "+f"(c[0]), "+f"(c[1]), "+f"(c[2]), "+f"(c[3])
        : "r"(a[0]), "r"(a[1]), "r"(a[2]), "r"(a[3]), "r"(b0), "r"(b1));
}

#define LDSM_X4(r0, r1, r2, r3, addr) \
    asm volatile("ldmatrix.sync.aligned.m8n8.x4.shared.b16 {%0,%1,%2,%3}, [%4];" \
                 : "=r"(r0), "=r"(r1), "=r"(r2), "=r"(r3) : "r"(addr))

__device__ __forceinline__ void cp16(uint32_t dst, const void* src, uint32_t bytes) {
    asm volatile("cp.async.cg.shared.global [%0], [%1], 16, %2;"
                 :: "r"(dst), "l"(src), "r"(bytes));
}
#define CP_COMMIT() asm volatile("cp.async.commit_group;" ::: "memory")
#define CP_WAIT(n)  asm volatile("cp.async.wait_group %0;" :: "n"(n) : "memory")

__device__ __forceinline__ void split4(float4 v, uint2& hi, uint2& lo) {
    __nv_bfloat16 hx = __float2bfloat16(v.x);
    __nv_bfloat16 hy = __float2bfloat16(v.y);
    __nv_bfloat16 hz = __float2bfloat16(v.z);
    __nv_bfloat16 hw = __float2bfloat16(v.w);
    __nv_bfloat16 lx = __float2bfloat16(v.x - __bfloat162float(hx));
    __nv_bfloat16 ly = __float2bfloat16(v.y - __bfloat162float(hy));
    __nv_bfloat16 lz = __float2bfloat16(v.z - __bfloat162float(hz));
    __nv_bfloat16 lw = __float2bfloat16(v.w - __bfloat162float(hw));
    hi.x = ((uint32_t)__bfloat16_as_ushort(hy) << 16) | __bfloat16_as_ushort(hx);
    hi.y = ((uint32_t)__bfloat16_as_ushort(hw) << 16) | __bfloat16_as_ushort(hz);
    lo.x = ((uint32_t)__bfloat16_as_ushort(ly) << 16) | __bfloat16_as_ushort(lx);
    lo.y = ((uint32_t)__bfloat16_as_ushort(lw) << 16) | __bfloat16_as_ushort(lz);
}

__device__ __forceinline__ void split2(float2 v, uint32_t& hi, uint32_t& lo) {
    __nv_bfloat16 hx = __float2bfloat16(v.x);
    __nv_bfloat16 hy = __float2bfloat16(v.y);
    __nv_bfloat16 lx = __float2bfloat16(v.x - __bfloat162float(hx));
    __nv_bfloat16 ly = __float2bfloat16(v.y - __bfloat162float(hy));
    hi = ((uint32_t)__bfloat16_as_ushort(hy) << 16) | __bfloat16_as_ushort(hx);
    lo = ((uint32_t)__bfloat16_as_ushort(ly) << 16) | __bfloat16_as_ushort(lx);
}

// ---------------- graph preprocessing ----------------
__global__ void zero_counts() {
    int i = blockIdx.x * blockDim.x + threadIdx.x;
    if (i < N_NODES) { g_cnt[i] = 0; g_fill[i] = 0; }
}
__global__ void count_deg(const int* __restrict__ rows) {
    int e = blockIdx.x * blockDim.x + threadIdx.x;
    if (e < N_EDGES) atomicAdd(&g_cnt[rows[e]], 1);
}
__global__ void compute_dinv() {
    int i = blockIdx.x * blockDim.x + threadIdx.x;
    if (i < N_NODES) g_dinv[i] = 1.0f / (float)(g_cnt[i] + 1);
}
__global__ void scan_blocks() {
    __shared__ int s[SCAN_T];
    int t   = threadIdx.x;
    int gid = blockIdx.x * SCAN_T + t;
    int v   = (gid < N_NODES) ? g_cnt[gid] : 0;
    s[t] = v;
    __syncthreads();
    #pragma unroll
    for (int off = 1; off < SCAN_T; off <<= 1) {
        int x = (t >= off) ? s[t - off] : 0;
        __syncthreads();
        s[t] += x;
        __syncthreads();
    }
    if (gid < N_NODES) g_rowstart[gid] = s[t] - v;
    if (t == SCAN_T - 1) g_bsum[blockIdx.x] = s[t];
}
__global__ void scan_offsets() {
    if (threadIdx.x == 0 && blockIdx.x == 0) {
        int acc = 0;
        for (int i = 0; i < NBLK; i++) { int t = g_bsum[i]; g_bsum[i] = acc; acc += t; }
        g_rowstart[N_NODES] = acc;
    }
}
__global__ void scan_add() {
    int t   = threadIdx.x;
    int gid = blockIdx.x * SCAN_T + t;
    if (gid < N_NODES) g_rowstart[gid] += g_bsum[blockIdx.x];
}
__global__ void scatter_edges(const int* __restrict__ rows, const int* __restrict__ cols) {
    int e = blockIdx.x * blockDim.x + threadIdx.x;
    if (e < N_EDGES) {
        int r   = rows[e];
        int pos = g_rowstart[r] + atomicAdd(&g_fill[r], 1);
        g_cols[pos] = cols[e];
    }
}
__global__ void split_w(const float* __restrict__ src, __nv_bfloat16* __restrict__ hi,
                        __nv_bfloat16* __restrict__ lo, int n) {
    int i = blockIdx.x * 256 + threadIdx.x;
    if (i < n) {
        float v = src[i];
        __nv_bfloat16 h = __float2bfloat16(v);
        hi[i] = h;
        lo[i] = __float2bfloat16(v - __bfloat162float(h));
    }
}

// ====== HMMA GEMM, bf16 3-term split, K-tile 32, 2-stage cp.async pipeline ======
#define RSB 80             // smem row stride bytes (64B data + 16B pad)

template<int BN, int RELU, int ABF16, int OUTSPLIT>
__global__ __launch_bounds__(256, 2)
void gemm_hmma(const float* __restrict__ Af,
               const __nv_bfloat16* __restrict__ Ahi_g,
               const __nv_bfloat16* __restrict__ Alo_g,
               const __nv_bfloat16* __restrict__ Whi_g,
               const __nv_bfloat16* __restrict__ Wlo_g,
               const float* __restrict__ bias,
               float* __restrict__ C,
               __nv_bfloat16* __restrict__ Chi,
               __nv_bfloat16* __restrict__ Clo,
               int Nrows, int Mcols, int K)
{
    constexpr int NJ      = BN / 16;
    constexpr int ABYTES  = 128 * RSB;                   // 10240
    constexpr int BBYTES  = BN * RSB;
    constexpr int STAGE   = 2 * ABYTES + 2 * BBYTES;     // AHI|ALO|BHI|BLO
    constexpr int OFF_BS  = 2 * STAGE;
    constexpr int BCHUNKS = BN / 64;                     // cp.async 16B iters for B

    extern __shared__ __align__(16) char sm[];

    const uint32_t smb = smem_u32(sm);
    const int tid = threadIdx.x;
    const int wid = tid >> 5;
    const int lid = tid & 31;
    const int warpM = (wid & 3) * 32;
    const int warpN = (wid >> 2) * (BN / 2);
    const int rowBase = blockIdx.y * 128;
    const int colBase = blockIdx.x * BN;
    const int NT = K / 32;

    // bias -> smem
    for (int i = tid; i < BN; i += 256) {
        int gc = colBase + i;
        *(float*)(sm + OFF_BS + i * 4) = (gc < Mcols) ? bias[gc] : 0.0f;
    }

    // per-lane ldmatrix address components
    const int aRow  = (lid & 7) + ((lid >> 3) & 1) * 8;
    const int aColB = (lid >> 4) * 16;
    const int bN    = ((lid >> 4) * 8) + (lid & 7);
    const int bColB = ((lid >> 3) & 1) * 16;

    const uint32_t aAddr0 = smb + (warpM + aRow) * RSB + aColB;
    const uint32_t bAddr0 = smb + 2 * ABYTES + (warpN + bN) * RSB + bColB;

    float acc[2][NJ][4];
    #pragma unroll
    for (int i = 0; i < 2; i++)
        #pragma unroll
        for (int j = 0; j < NJ; j++)
            #pragma unroll
            for (int q = 0; q < 4; q++) acc[i][j][q] = 0.0f;

    float4 paf[4];   // fp32-A prefetch (ABF16=0 only)

    // cp.async A (bf16 path): 128x32 hi + lo, 2 chunks each per thread
    auto cpA = [&](int t, int st) {
        const int kt = t * 32;
        char* base = sm + st * STAGE;
        #pragma unroll
        for (int i = 0; i < 2; i++) {
            int idx = tid + i * 256;
            int row = idx >> 2;
            int c   = idx & 3;
            int gr  = rowBase + row;
            uint32_t sz = (gr < Nrows) ? 16u : 0u;
            int gra = (gr < Nrows) ? gr : 0;
            uint32_t so = smem_u32(base + row * RSB + c * 16);
            cp16(so,          Ahi_g + (size_t)gra * K + kt + c * 8, sz);
            cp16(so + ABYTES, Alo_g + (size_t)gra * K + kt + c * 8, sz);
        }
    };
    // cp.async B: BN x 32 hi + lo
    auto cpB = [&](int t, int st) {
        const int kt = t * 32;
        char* base = sm + st * STAGE + 2 * ABYTES;
        #pragma unroll
        for (int i = 0; i < BCHUNKS; i++) {
            int idx = tid + i * 256;
            int row = idx >> 2;
            int c   = idx & 3;
            int gm  = colBase + row;
            uint32_t sz = (gm < Mcols) ? 16u : 0u;
            int gma = (gm < Mcols) ? gm : 0;
            uint32_t so = smem_u32(base + row * RSB + c * 16);
            cp16(so,          Whi_g + (size_t)gma * K + kt + c * 8, sz);
            cp16(so + BBYTES, Wlo_g + (size_t)gma * K + kt + c * 8, sz);
        }
    };
    // fp32 A prefetch to regs (ABF16=0): 128x32 fp32, 4 float4/thread
    auto ldA = [&](int t) {
        const int kt = t * 32;
        #pragma unroll
        for (int i = 0; i < 4; i++) {
            int idx = tid + i * 256;
            int row = idx >> 3;
            int c4  = idx & 7;
            int gr  = rowBase + row;
            paf[i] = make_float4(0.f, 0.f, 0.f, 0.f);
            if (gr < Nrows) paf[i] = *(const float4*)(Af + (size_t)gr * K + kt + c4 * 4);
        }
    };
    auto stsA = [&](int st) {
        char* base = sm + st * STAGE;
        #pragma unroll
        for (int i = 0; i < 4; i++) {
            int idx = tid + i * 256;
            int row = idx >> 3;
            int c4  = idx & 7;
            uint2 hi, lo; split4(paf[i], hi, lo);
            *(uint2*)(base + row * RSB + c4 * 8) = hi;
            *(uint2*)(base + ABYTES + row * RSB + c4 * 8) = lo;
        }
    };

    auto MMA = [&](int st) {
        const uint32_t aA = aAddr0 + st * STAGE;
        const uint32_t bA = bAddr0 + st * STAGE;
        #pragma unroll
        for (int ks = 0; ks < 2; ks++) {
            const uint32_t kOff = ks * 32;
            uint32_t ah[2][4], al[2][4];
            #pragma unroll
            for (int i = 0; i < 2; i++) {
                uint32_t aa = aA + i * 16 * RSB + kOff;
                LDSM_X4(ah[i][0], ah[i][1], ah[i][2], ah[i][3], aa);
                LDSM_X4(al[i][0], al[i][1], al[i][2], al[i][3], aa + ABYTES);
            }
            #pragma unroll
            for (int jp = 0; jp < NJ / 2; jp++) {
                uint32_t bb = bA + jp * 16 * RSB + kOff;
                uint32_t bh0, bh1, bh2, bh3, bl0, bl1, bl2, bl3;
                LDSM_X4(bh0, bh1, bh2, bh3, bb);
                LDSM_X4(bl0, bl1, bl2, bl3, bb + BBYTES);
                #pragma unroll
                for (int i = 0; i < 2; i++) {
                    mma16816(acc[i][2 * jp],     ah[i], bh0, bh1);
                    mma16816(acc[i][2 * jp],     ah[i], bl0, bl1);
                    mma16816(acc[i][2 * jp],     al[i], bh0, bh1);
                    mma16816(acc[i][2 * jp + 1], ah[i], bh2, bh3);
                    mma16816(acc[i][2 * jp + 1], ah[i], bl2, bl3);
                    mma16816(acc[i][2 * jp + 1], al[i], bh2, bh3);
                }
            }
        }
    };

    // ---- prologue: stage 0 in flight ----
    if (ABF16) cpA(0, 0); else ldA(0);
    cpB(0, 0);
    CP_COMMIT();

    // ---- mainloop ----
    for (int t = 0; t < NT; t++) {
        const int st = t & 1;
        if (!ABF16) stsA(st);                 // A(t) regs -> smem
        if (t + 1 < NT) {
            const int sn = (t + 1) & 1;
            if (ABF16) cpA(t + 1, sn); else ldA(t + 1);
            cpB(t + 1, sn);
        }
        CP_COMMIT();
        if (t + 1 < NT) { CP_WAIT(1); } else { CP_WAIT(0); }
        __syncthreads();
        MMA(st);
        __syncthreads();
    }

    // ---- epilogue ----
    const int rBase = rowBase + warpM + (lid >> 2);
    const int cOff  = warpN + (lid & 3) * 2;
    #pragma unroll
    for (int i = 0; i < 2; i++) {
        #pragma unroll
        for (int j = 0; j < NJ; j++) {
            int cl = cOff + j * 8;
            int gc = colBase + cl;
            if (gc >= Mcols) continue;
            float2 bb = *(const float2*)(sm + OFF_BS + cl * 4);
            int r0 = rBase + i * 16;
            int r1 = r0 + 8;
            float2 v0, v1;
            v0.x = acc[i][j][0] + bb.x; v0.y = acc[i][j][1] + bb.y;
            v1.x = acc[i][j][2] + bb.x; v1.y = acc[i][j][3] + bb.y;
            if (RELU) {
                v0.x = fmaxf(v0.x, 0.f); v0.y = fmaxf(v0.y, 0.f);
                v1.x = fmaxf(v1.x, 0.f); v1.y = fmaxf(v1.y, 0.f);
            }
            if (OUTSPLIT) {
                uint32_t h0, l0, h1v, l1;
                split2(v0, h0, l0);
                split2(v1, h1v, l1);
                if (r0 < Nrows) {
                    *(uint32_t*)(Chi + (size_t)r0 * Mcols + gc) = h0;
                    *(uint32_t*)(Clo + (size_t)r0 * Mcols + gc) = l0;
                }
                if (r1 < Nrows) {
                    *(uint32_t*)(Chi + (size_t)r1 * Mcols + gc) = h1v;
                    *(uint32_t*)(Clo + (size_t)r1 * Mcols + gc) = l1;
                }
            } else {
                if (r0 < Nrows) *(float2*)(C + (size_t)r0 * Mcols + gc) = v0;
                if (r1 < Nrows) *(float2*)(C + (size_t)r1 * Mcols + gc) = v1;
            }
        }
    }
}

// ---------------- SpMM power-iteration step ----------------
__global__ __launch_bounds__(320)
void spmm_step(const float4* __restrict__ v4, const float4* __restrict__ h4,
               float4* __restrict__ out4)
{
    int t = blockIdx.x * 320 + threadIdx.x;
    int r = t / NF4;
    int f = t - r * NF4;
    if (r >= N_NODES) return;

    int s = g_rowstart[r];
    int e = g_rowstart[r + 1];

    float ax = 0.f, ay = 0.f, az = 0.f, aw = 0.f;
    int i = s;
    for (; i + 4 <= e; i += 4) {
        int c0 = g_cols[i + 0], c1 = g_cols[i + 1];
        int c2 = g_cols[i + 2], c3 = g_cols[i + 3];
        float4 p0 = __ldg(v4 + (size_t)c0 * NF4 + f);
        float4 p1 = __ldg(v4 + (size_t)c1 * NF4 + f);
        float4 p2 = __ldg(v4 + (size_t)c2 * NF4 + f);
        float4 p3 = __ldg(v4 + (size_t)c3 * NF4 + f);
        ax += (p0.x + p1.x) + (p2.x + p3.x);
        ay += (p0.y + p1.y) + (p2.y + p3.y);
        az += (p0.z + p1.z) + (p2.z + p3.z);
        aw += (p0.w + p1.w) + (p2.w + p3.w);
    }
    for (; i < e; i++) {
        int c = g_cols[i];
        float4 p = __ldg(v4 + (size_t)c * NF4 + f);
        ax += p.x; ay += p.y; az += p.z; aw += p.w;
    }

    float4 vr = __ldg(v4 + (size_t)r * NF4 + f);
    float4 hr = __ldg(h4 + (size_t)r * NF4 + f);
    float  w  = 0.5f * g_dinv[r];

    float4 o;
    o.x = w * (ax + vr.x) + 0.5f * hr.x;
    o.y = w * (ay + vr.y) + 0.5f * hr.y;
    o.z = w * (az + vr.z) + 0.5f * hr.z;
    o.w = w * (aw + vr.w) + 0.5f * hr.w;
    out4[(size_t)r * NF4 + f] = o;
}

// ---------------- host ----------------
extern "C" void kernel_launch(void* const* d_in, const int* in_sizes, int n_in,
                              void* d_out, int out_size)
{
    const float* x  = (const float*)d_in[0];
    const int*   ei = (const int*)  d_in[1];
    const float* W1 = (const float*)d_in[2];
    const float* b1 = (const float*)d_in[3];
    const float* W2 = (const float*)d_in[4];
    const float* b2 = (const float*)d_in[5];
    const float* W3 = (const float*)d_in[6];
    const float* b3 = (const float*)d_in[7];
    float* out = (float*)d_out;

    const int* rows = ei;
    const int* cols = ei + N_EDGES;

    void *p;
    float *h1, *h2, *h, *vA, *vB;
    __nv_bfloat16 *w1hi, *w1lo, *w2hi, *w2lo, *w3hi, *w3lo;
    cudaGetSymbolAddress(&p, g_h1);   h1 = (float*)p;
    cudaGetSymbolAddress(&p, g_h2);   h2 = (float*)p;
    cudaGetSymbolAddress(&p, g_h);    h  = (float*)p;
    cudaGetSymbolAddress(&p, g_vA);   vA = (float*)p;
    cudaGetSymbolAddress(&p, g_vB);   vB = (float*)p;
    cudaGetSymbolAddress(&p, g_w1hi); w1hi = (__nv_bfloat16*)p;
    cudaGetSymbolAddress(&p, g_w1lo); w1lo = (__nv_bfloat16*)p;
    cudaGetSymbolAddress(&p, g_w2hi); w2hi = (__nv_bfloat16*)p;
    cudaGetSymbolAddress(&p, g_w2lo); w2lo = (__nv_bfloat16*)p;
    cudaGetSymbolAddress(&p, g_w3hi); w3hi = (__nv_bfloat16*)p;
    cudaGetSymbolAddress(&p, g_w3lo); w3lo = (__nv_bfloat16*)p;

    __nv_bfloat16* h1hi = (__nv_bfloat16*)h1;
    __nv_bfloat16* h1lo = h1hi + (size_t)N_NODES * NHID;
    __nv_bfloat16* h2hi = (__nv_bfloat16*)h2;
    __nv_bfloat16* h2lo = h2hi + (size_t)N_NODES * NHID;

    // side stream + events for CSR overlap (created fresh each call; host-only resources)
    cudaStream_t s1;
    cudaStreamCreateWithFlags(&s1, cudaStreamNonBlocking);
    cudaEvent_t evFork, evJoin;
    cudaEventCreateWithFlags(&evFork, cudaEventDisableTiming);
    cudaEventCreateWithFlags(&evJoin, cudaEventDisableTiming);

    // ---- fork: CSR build on side stream, concurrent with GEMM chain ----
    cudaEventRecord(evFork, 0);
    cudaStreamWaitEvent(s1, evFork, 0);
    zero_counts  <<<(N_NODES + 255) / 256, 256, 0, s1>>>();
    count_deg    <<<(N_EDGES + 255) / 256, 256, 0, s1>>>(rows);
    compute_dinv <<<(N_NODES + 255) / 256, 256, 0, s1>>>();
    scan_blocks  <<<NBLK, SCAN_T, 0, s1>>>();
    scan_offsets <<<1, 32, 0, s1>>>();
    scan_add     <<<NBLK, SCAN_T, 0, s1>>>();
    scatter_edges<<<(N_EDGES + 255) / 256, 256, 0, s1>>>(rows, cols);
    cudaEventRecord(evJoin, s1);

    // ---- main stream: weight splits (tiny) + GEMM chain ----
    split_w<<<(NHID * NFEAT  + 255) / 256, 256>>>(W1, w1hi, w1lo, NHID * NFEAT);
    split_w<<<(NHID * NHID   + 255) / 256, 256>>>(W2, w2hi, w2lo, NHID * NHID);
    split_w<<<(NCLASS * NHID + 255) / 256, 256>>>(W3, w3hi, w3lo, NCLASS * NHID);

    const int STG128 = 2 * (128 * RSB) + 2 * (128 * RSB);   // 40960
    const int STG64  = 2 * (128 * RSB) + 2 * (64 * RSB);    // 30720
    const int SMEM_128 = 2 * STG128 + 128 * 4;              // 82432
    const int SMEM_64  = 2 * STG64 + 64 * 4;                // 61696
    cudaFuncSetAttribute((const void*)gemm_hmma<128, 1, 0, 1>,
                         cudaFuncAttributeMaxDynamicSharedMemorySize, SMEM_128);
    cudaFuncSetAttribute((const void*)gemm_hmma<128, 1, 1, 1>,
                         cudaFuncAttributeMaxDynamicSharedMemorySize, SMEM_128);
    cudaFuncSetAttribute((const void*)gemm_hmma<64, 0, 1, 0>,
                         cudaFuncAttributeMaxDynamicSharedMemorySize, SMEM_64);

    const int MG = (N_NODES + 127) / 128;   // 782
    gemm_hmma<128, 1, 0, 1><<<dim3(2, MG), 256, SMEM_128>>>(
        x, nullptr, nullptr, w1hi, w1lo, b1, nullptr, h1hi, h1lo, N_NODES, NHID, NFEAT);
    gemm_hmma<128, 1, 1, 1><<<dim3(2, MG), 256, SMEM_128>>>(
        nullptr, h1hi, h1lo, w2hi, w2lo, b2, nullptr, h2hi, h2lo, N_NODES, NHID, NHID);
    gemm_hmma<64, 0, 1, 0><<<dim3(1, MG), 256, SMEM_64>>>(
        nullptr, h2hi, h2lo, w3hi, w3lo, b3, h, nullptr, nullptr, N_NODES, NCLASS, NHID);

    // ---- join: CSR must be done before propagation ----
    cudaStreamWaitEvent(0, evJoin, 0);

    // ---- 10 power iterations ----
    const int SP_G = (N_NODES * NF4 + 319) / 320;
    const float* src = h;
    for (int it = 0; it < 10; it++) {
        float* dst = (it == 9) ? out : ((it & 1) ? vB : vA);
        spmm_step<<<SP_G, 320>>>((const float4*)src, (const float4*)h, (float4*)dst);
        src = dst;
    }
}